// round 15
// baseline (speedup 1.0000x reference)
#include <cuda_runtime.h>
#include <math.h>

// ---------------------------------------------------------------------------
// SmoothAP (quick_forward, sigmoid rank approx, 1-mAP), B x B scores/target.
//
//   ap[b] = (1/np_b) * sum_{i in pos(b)} (P_i + np + 1) / (T_i + B + 1)
//   T_i = sum_j tanh(50*(s_j - s_i))            (diag tanh(0)=0)
//   P_i = sum_j tanh(50*(s_j - s_i)) * tg_j
//   out = 1 - mean_b ap[b]
//
// TWO ROWS PER BLOCK: grid 256 x 512 threads, warps 0-7 -> row 2b, 8-15 ->
// row 2b+1.  Pair-optimal MUFU (npos*B tanh).  Folded paired reduction:
// one xor-16 fold per accumulator, halves select positive 1 vs 2, then a
// single shared 4-level butterfly reduces both at once (26 instrs vs 40).
// Block publishes one atomicAdd + ticket; last block finalizes and re-arms.
// ---------------------------------------------------------------------------

#define KSCALE 50.0f        // 1/(2*tau)

__device__ float        g_accum;          // zero at load; re-armed each run
__device__ unsigned int g_count = 0;      // ticket counter; re-armed each run

__device__ __forceinline__ float tanha(float x) {
    float r; asm("tanh.approx.f32 %0, %1;" : "=f"(r) : "f"(x)); return r;
}
__device__ __forceinline__ float ex2a(float x) {
    float r; asm("ex2.approx.f32 %0, %1;" : "=f"(r) : "f"(x)); return r;
}
__device__ __forceinline__ float rcpa(float x) {
    float r; asm("rcp.approx.f32 %0, %1;" : "=f"(r) : "f"(x)); return r;
}

// ---------------- fused kernel: B == 512, 2 rows/block, 512 threads ---------
__global__ void __launch_bounds__(512)
sap512_2row(const float* __restrict__ scores,
            const float* __restrict__ target,
            float* __restrict__ out) {
    constexpr int B = 512;
    __shared__ __align__(16) float ssK[2 * B];  // rows 2b,2b+1 * KSCALE
    __shared__ __align__(16) float st[2 * B];   // target rows
    __shared__ float wsum[16];
    __shared__ int   wcnt[32];
    __shared__ short plist[2 * B];              // row0 at [0..], row1 at [512..]

    const int bb   = blockIdx.x;                // handles rows 2bb, 2bb+1
    const int tid  = threadIdx.x;
    const int lane = tid & 31;
    const int warp = tid >> 5;

    // ---- prologue: one LDG.128 per thread (rows are contiguous) ------------
    {
        const float4* s4g = (const float4*)(scores + (size_t)bb * 2 * B);
        const float4* t4g = (const float4*)(target + (size_t)bb * 2 * B);
        if (tid < 256) {
            float4 v = s4g[tid];
            ((float4*)ssK)[tid] = make_float4(v.x * KSCALE, v.y * KSCALE,
                                              v.z * KSCALE, v.w * KSCALE);
        } else {
            ((float4*)st)[tid - 256] = t4g[tid - 256];
        }
    }
    __syncthreads();

    // ---- compaction: 32 groups (16 per row), one full-warp scan ------------
    const bool p0 = (st[tid]       != 0.0f);
    const bool p1 = (st[tid + 512] != 0.0f);
    const unsigned m0 = __ballot_sync(0xffffffffu, p0);
    const unsigned m1 = __ballot_sync(0xffffffffu, p1);
    if (lane == 0) { wcnt[warp] = __popc(m0); wcnt[16 + warp] = __popc(m1); }
    __syncthreads();

    int c   = wcnt[lane];
    int inc = c;
#pragma unroll
    for (int o = 1; o < 32; o <<= 1) {
        int t = __shfl_up_sync(0xffffffffu, inc, o);
        if (lane >= o) inc += t;
    }
    const int n0 = __shfl_sync(0xffffffffu, inc, 15);             // row0 npos
    const int n1 = __shfl_sync(0xffffffffu, inc, 31) - n0;        // row1 npos
    const int exc     = inc - c;
    const int before0 = __shfl_sync(0xffffffffu, exc, warp);
    const int before1 = __shfl_sync(0xffffffffu, exc, 16 + warp) - n0;
    const unsigned lt = (1u << lane) - 1u;
    if (p0) plist[before0 + __popc(m0 & lt)]       = (short)tid;
    if (p1) plist[512 + before1 + __popc(m1 & lt)] = (short)(tid + 512);
    __syncthreads();

    // ---- main: warps 0-7 -> row0, warps 8-15 -> row1; 2 pos per trip -------
    const int   r    = warp >> 3;               // my row (0/1)
    const int   wr   = warp & 7;                // warp index within row group
    const int   nr   = r ? n1 : n0;
    const float4* ss4 = (const float4*)ssK + r * (B / 4);
    const float4* st4 = (const float4*)st  + r * (B / 4);
    const short* pl  = plist + r * B;
    const float numc = (float)(nr + 1);
    const float denc = (float)(B + 1);
    float sum_r = 0.0f;                         // lanes<16: ratio1; >=16: ratio2
    for (int k = wr * 2; k < nr; k += 16) {
        const bool  has2 = (k + 1 < nr);
        const float si1  = ssK[pl[k]];
        const float si2  = ssK[pl[has2 ? k + 1 : k]];
        float T1 = 0.0f, P1 = 0.0f, T2 = 0.0f, P2 = 0.0f;
#pragma unroll
        for (int q = 0; q < B / 128; ++q) {
            float4 s4 = ss4[q * 32 + lane];
            float4 t4 = st4[q * 32 + lane];
            float a0 = tanha(s4.x - si1), b0 = tanha(s4.x - si2);
            float a1 = tanha(s4.y - si1), b1 = tanha(s4.y - si2);
            float a2 = tanha(s4.z - si1), b2 = tanha(s4.z - si2);
            float a3 = tanha(s4.w - si1), b3 = tanha(s4.w - si2);
            T1 += (a0 + a1) + (a2 + a3);
            T2 += (b0 + b1) + (b2 + b3);
            P1 = fmaf(a0, t4.x, fmaf(a1, t4.y, fmaf(a2, t4.z, fmaf(a3, t4.w, P1))));
            P2 = fmaf(b0, t4.x, fmaf(b1, t4.y, fmaf(b2, t4.z, fmaf(b3, t4.w, P2))));
        }
        // folded paired reduction: fold 16, select halves, shared 4-level tree
        T1 += __shfl_xor_sync(0xffffffffu, T1, 16);
        T2 += __shfl_xor_sync(0xffffffffu, T2, 16);
        P1 += __shfl_xor_sync(0xffffffffu, P1, 16);
        P2 += __shfl_xor_sync(0xffffffffu, P2, 16);
        float Tm = (lane < 16) ? T1 : T2;
        float Pm = (lane < 16) ? P1 : P2;
#pragma unroll
        for (int o = 8; o; o >>= 1) {
            Tm += __shfl_xor_sync(0xffffffffu, Tm, o);
            Pm += __shfl_xor_sync(0xffffffffu, Pm, o);
        }
        float rr = __fdividef(Pm + numc, Tm + denc);
        if (lane >= 16 && !has2) rr = 0.0f;
        sum_r += rr;
    }
    // merge the two half-warp ratio streams; lane 0 holds the warp total
    sum_r += __shfl_xor_sync(0xffffffffu, sum_r, 16);
    if (lane == 0) wsum[warp] = __fdividef(sum_r, (float)nr);
    __syncthreads();

    // ---- block reduce -> one atomicAdd + ticket; last block finalizes ------
    if (warp == 0) {
        float bs = (lane < 16) ? wsum[lane] : 0.0f;
#pragma unroll
        for (int o = 8; o; o >>= 1) bs += __shfl_xor_sync(0xffffffffu, bs, o);
        if (lane == 0) {
            atomicAdd(&g_accum, bs);
            __threadfence();
            unsigned old = atomicAdd(&g_count, 1u);
            if (old == (unsigned)(gridDim.x - 1)) {
                float tot = atomicAdd(&g_accum, 0.0f);   // all adds L2-visible
                out[0] = 1.0f - tot * (1.0f / 512.0f);
                atomicExch(&g_accum, 0.0f);
                atomicExch(&g_count, 0u);                // re-arm for replay
            }
        }
    }
}

// ---------------- generic fallback (any B) ----------------------------------
__global__ void sap_generic_kernel(const float* __restrict__ scores,
                                   const float* __restrict__ target,
                                   float* __restrict__ out, int B) {
    extern __shared__ float sh[];
    float* ss   = sh;
    float* st   = sh + B;
    float* wred = sh + 2 * B;
    __shared__ bool isLast;

    const int b      = blockIdx.x;
    const int tid    = threadIdx.x;
    const int lane   = tid & 31;
    const int warp   = tid >> 5;
    const int nwarps = blockDim.x >> 5;

    const float* srow = scores + (size_t)b * B;
    const float* trow = target + (size_t)b * B;
    for (int j = tid; j < B; j += blockDim.x) {
        ss[j] = srow[j] * 144.26950408889634f;   // (1/tau)*log2e
        st[j] = trow[j];
    }
    __syncthreads();

    float sum_r = 0.0f;
    for (int i = warp; i < B; i += nwarps) {
        if (st[i] == 0.0f) continue;
        const float siK = ss[i];
        float A = 0.0f, P = 0.0f;
        for (int j = lane; j < B; j += 32) {
            float g = rcpa(1.0f + ex2a(siK - ss[j]));
            A += g;
            P = fmaf(g, st[j], P);
        }
#pragma unroll
        for (int o = 16; o; o >>= 1) {
            A += __shfl_xor_sync(0xffffffffu, A, o);
            P += __shfl_xor_sync(0xffffffffu, P, o);
        }
        sum_r += __fdividef(P + 0.5f, A + 0.5f);
    }
    if (lane == 0) wred[warp] = sum_r;
    __syncthreads();

    if (warp == 0) {
        float np = 0.0f;
        for (int j = lane; j < B; j += 32) np += st[j];
#pragma unroll
        for (int o = 16; o; o >>= 1) np += __shfl_xor_sync(0xffffffffu, np, o);
        float bs = (lane < nwarps) ? wred[lane] : 0.0f;
#pragma unroll
        for (int o = 16; o; o >>= 1) bs += __shfl_xor_sync(0xffffffffu, bs, o);
        if (lane == 0) {
            atomicAdd(&g_accum, __fdividef(bs, np));
            __threadfence();
            unsigned old = atomicAdd(&g_count, 1u);
            isLast = (old == (unsigned)gridDim.x - 1u);
        }
    }
    __syncthreads();
    if (isLast && tid == 0) {
        __threadfence();
        float tot = atomicAdd(&g_accum, 0.0f);
        out[0] = 1.0f - tot / (float)B;
        atomicExch(&g_accum, 0.0f);
        atomicExch(&g_count, 0u);
    }
}

extern "C" void kernel_launch(void* const* d_in, const int* in_sizes, int n_in,
                              void* d_out, int out_size) {
    const float* scores = (const float*)d_in[0];
    const float* target = (const float*)d_in[1];
    float* out = (float*)d_out;

    int n = in_sizes[0];
    int B = 1;
    while ((long long)B * B < (long long)n) ++B;

    if (B == 512) {
        sap512_2row<<<256, 512>>>(scores, target, out);
    } else {
        int threads = 512;
        if (threads > B) {
            threads = ((B + 31) / 32) * 32;
            if (threads < 32) threads = 32;
        }
        size_t smem = (size_t)2 * B * sizeof(float) + 32 * sizeof(float);
        sap_generic_kernel<<<B, threads, smem>>>(scores, target, out, B);
    }
}